// round 9
// baseline (speedup 1.0000x reference)
#include <cuda_runtime.h>
#include <cuda_fp16.h>
#include <cstdint>

#define TOKENS 32768
#define HIDDEN 2048

// GEMM tiling
#define BM 128
#define BN 128
#define BKH 64              // K elements (halves) per stage
#define STAGES 3
#define NKB2 (HIDDEN / BKH) // 32
#define AS_BYTES (BM * BKH * 2)   // 16384
#define BS_BYTES (BN * BKH * 2)   // 16384
#define STG_BYTES (AS_BYTES + BS_BYTES)  // 32768
#define GEMM_SMEM (STAGES * STG_BYTES)   // 98304

static constexpr float EPS = 1e-6f;

// ---------------- scratch (device globals; no allocation allowed) -------------
__device__ float  g_resid[(size_t)TOKENS * HIDDEN];           // 256 MB fp32 residual
__device__ __half g_yh  [(size_t)TOKENS * HIDDEN];            // 128 MB fp16 activations (row major)
__device__ __half g_wh  [(size_t)3 * HIDDEN * HIDDEN];        // 24 MB fp16 W^T: [w][n][k]

// ---------------- helpers -----------------------------------------------------
__device__ __forceinline__ uint32_t smem_u32(const void* p) {
    uint32_t a;
    asm("{ .reg .u64 t; cvta.to.shared.u64 t, %1; cvt.u32.u64 %0, t; }" : "=r"(a) : "l"(p));
    return a;
}
// SW128 swizzle on byte offsets (rows of 128B)
__device__ __forceinline__ uint32_t swz(uint32_t o) { return o ^ ((o >> 3) & 0x70); }

__device__ __forceinline__ void cp_async16(uint32_t saddr, const void* gaddr) {
    asm volatile("cp.async.cg.shared.global [%0], [%1], 16;" :: "r"(saddr), "l"(gaddr) : "memory");
}
__device__ __forceinline__ void cp_commit() {
    asm volatile("cp.async.commit_group;" ::: "memory");
}
template <int N>
__device__ __forceinline__ void cp_wait() {
    asm volatile("cp.async.wait_group %0;" :: "n"(N) : "memory");
}
__device__ __forceinline__ void ldsm4(uint32_t& r0, uint32_t& r1, uint32_t& r2, uint32_t& r3,
                                      uint32_t addr) {
    asm volatile("ldmatrix.sync.aligned.m8n8.x4.shared.b16 {%0,%1,%2,%3}, [%4];"
                 : "=r"(r0), "=r"(r1), "=r"(r2), "=r"(r3) : "r"(addr));
}
__device__ __forceinline__ void mma16816(float* c, const uint32_t* a, const uint32_t* b) {
    asm volatile(
        "mma.sync.aligned.m16n8k16.row.col.f32.f16.f16.f32 "
        "{%0,%1,%2,%3}, {%4,%5,%6,%7}, {%8,%9}, {%0,%1,%2,%3};"
        : "+f"(c[0]), "+f"(c[1]), "+f"(c[2]), "+f"(c[3])
        : "r"(a[0]), "r"(a[1]), "r"(a[2]), "r"(a[3]), "r"(b[0]), "r"(b[1]));
}

// ---------------- block-wide sum reduce ---------------------------------------
__device__ __forceinline__ float blk_sum(float v) {
    __shared__ float red[8];
    #pragma unroll
    for (int o = 16; o; o >>= 1) v += __shfl_xor_sync(0xFFFFFFFFu, v, o);
    if ((threadIdx.x & 31) == 0) red[threadIdx.x >> 5] = v;
    __syncthreads();
    float s = 0.f;
    #pragma unroll
    for (int i = 0; i < 8; i++) s += red[i];
    __syncthreads();
    return s;
}

// ---------------- weight transpose + fp16 convert: g_wh[w][n][k] = W[k][n] ----
__global__ void __launch_bounds__(256) k_wprep(const float* __restrict__ W0,
                                               const float* __restrict__ W1,
                                               const float* __restrict__ W2) {
    const float* W = (blockIdx.z == 0) ? W0 : (blockIdx.z == 1) ? W1 : W2;
    __shared__ float t[32][33];
    int n0 = blockIdx.x * 32, k0 = blockIdx.y * 32;
    int tx = threadIdx.x, ty = threadIdx.y;
    #pragma unroll
    for (int i = 0; i < 4; i++)
        t[ty + 8 * i][tx] = W[(size_t)(k0 + ty + 8 * i) * HIDDEN + n0 + tx];
    __syncthreads();
    __half* dst = g_wh + (size_t)blockIdx.z * HIDDEN * HIDDEN;
    #pragma unroll
    for (int i = 0; i < 4; i++) {
        int n = n0 + ty + 8 * i;
        dst[(size_t)n * HIDDEN + k0 + tx] = __float2half_rn(t[tx][ty + 8 * i]);
    }
}

// ---------------- yh store helper (fp16 row-major) ----------------------------
__device__ __forceinline__ uint32_t h2_as_u32(__half2 h) {
    return *reinterpret_cast<uint32_t*>(&h);
}
__device__ __forceinline__ void yh_store4(int t, int j, float4 v) {
    uint2 p;
    p.x = h2_as_u32(__floats2half2_rn(v.x, v.y));
    p.y = h2_as_u32(__floats2half2_rn(v.z, v.w));
    ((uint2*)(g_yh + (size_t)t * HIDDEN))[j] = p;
}

// ---------------- prologue: relu -> resid, rmsnorm(g0) -> yh ------------------
__global__ void __launch_bounds__(256) k_prologue(const float* __restrict__ x,
                                                  const float* __restrict__ g) {
    int t = blockIdx.x;
    int tid = threadIdx.x;
    const float4* xr = (const float4*)(x + (size_t)t * HIDDEN);
    float4* rr = (float4*)(g_resid + (size_t)t * HIDDEN);
    float4 v0 = xr[tid], v1 = xr[tid + 256];
    v0.x = fmaxf(v0.x, 0.f); v0.y = fmaxf(v0.y, 0.f); v0.z = fmaxf(v0.z, 0.f); v0.w = fmaxf(v0.w, 0.f);
    v1.x = fmaxf(v1.x, 0.f); v1.y = fmaxf(v1.y, 0.f); v1.z = fmaxf(v1.z, 0.f); v1.w = fmaxf(v1.w, 0.f);
    rr[tid] = v0; rr[tid + 256] = v1;
    float ss = v0.x*v0.x + v0.y*v0.y + v0.z*v0.z + v0.w*v0.w
             + v1.x*v1.x + v1.y*v1.y + v1.z*v1.z + v1.w*v1.w;
    float tot = blk_sum(ss);
    float scale = rsqrtf(tot / (float)HIDDEN + EPS);
    const float4* gr = (const float4*)g;
    float4 gv0 = gr[tid], gv1 = gr[tid + 256];
    float4 y0 = { v0.x*scale*gv0.x, v0.y*scale*gv0.y, v0.z*scale*gv0.z, v0.w*scale*gv0.w };
    float4 y1 = { v1.x*scale*gv1.x, v1.y*scale*gv1.y, v1.z*scale*gv1.z, v1.w*scale*gv1.w };
    yh_store4(t, tid, y0);
    yh_store4(t, tid + 256, y1);
}

// ---------------- norm: read resid, rmsnorm(g) -> yh (fp16) or out (fp32) -----
__global__ void __launch_bounds__(256) k_norm(const float* __restrict__ g,
                                              float* __restrict__ out) {
    int t = blockIdx.x;
    int tid = threadIdx.x;
    const float4* xr = (const float4*)(g_resid + (size_t)t * HIDDEN);
    float4 v0 = xr[tid], v1 = xr[tid + 256];
    float ss = v0.x*v0.x + v0.y*v0.y + v0.z*v0.z + v0.w*v0.w
             + v1.x*v1.x + v1.y*v1.y + v1.z*v1.z + v1.w*v1.w;
    float tot = blk_sum(ss);
    float scale = rsqrtf(tot / (float)HIDDEN + EPS);
    const float4* gr = (const float4*)g;
    float4 gv0 = gr[tid], gv1 = gr[tid + 256];
    float4 y0 = { v0.x*scale*gv0.x, v0.y*scale*gv0.y, v0.z*scale*gv0.z, v0.w*scale*gv0.w };
    float4 y1 = { v1.x*scale*gv1.x, v1.y*scale*gv1.y, v1.z*scale*gv1.z, v1.w*scale*gv1.w };
    if (out) {
        float4* o = (float4*)(out + (size_t)t * HIDDEN);
        o[tid] = y0; o[tid + 256] = y1;
    } else {
        yh_store4(t, tid, y0);
        yh_store4(t, tid + 256, y1);
    }
}

// ---------------- fp16 mma.sync GEMM: resid[M,N] += yh @ W --------------------
// CTA tile 128x128, K-stage 64 halves, 3-stage cp.async pipeline.
// smem tiles: As[128][64] halves, Bs[128][64] halves (B rows are N, k contig),
// both SW128-swizzled per 128B row.
__global__ void __launch_bounds__(256) k_gemm(int widx) {
    extern __shared__ char smraw[];
    uint32_t smBase = smem_u32(smraw);

    int tid = threadIdx.x;
    int lane = tid & 31, wid = tid >> 5;
    int warpM = wid & 3, warpN = wid >> 2;      // 4 x 2 warps
    int m0 = blockIdx.y * BM, n0 = blockIdx.x * BN;

    const __half* aG = g_yh + (size_t)m0 * HIDDEN;
    const __half* bG = g_wh + (size_t)widx * HIDDEN * HIDDEN + (size_t)n0 * HIDDEN;

    // per-thread cp.async source/dest pattern: 16B chunks
    int c16 = tid & 7;        // chunk within 128B row
    int rr  = tid >> 3;       // 0..31, +32*i for 4 rounds

    auto ld_stage = [&](int st, int kb) {
        uint32_t sA = smBase + st * STG_BYTES;
        uint32_t sB = sA + AS_BYTES;
        const __half* ga = aG + (size_t)kb * BKH + (size_t)c16 * 8;
        const __half* gb = bG + (size_t)kb * BKH + (size_t)c16 * 8;
        #pragma unroll
        for (int i = 0; i < 4; i++) {
            int r = rr + 32 * i;
            cp_async16(sA + swz(r * 128 + c16 * 16), ga + (size_t)r * HIDDEN);
            cp_async16(sB + swz(r * 128 + c16 * 16), gb + (size_t)r * HIDDEN);
        }
    };

    // prologue
    #pragma unroll
    for (int s = 0; s < STAGES - 1; s++) { ld_stage(s, s); cp_commit(); }

    float acc[2][8][4];
    #pragma unroll
    for (int mf = 0; mf < 2; mf++)
        #pragma unroll
        for (int nf = 0; nf < 8; nf++)
            #pragma unroll
            for (int i = 0; i < 4; i++) acc[mf][nf][i] = 0.f;

    // ldmatrix per-lane row indices
    int aRow = warpM * 32 + (lane & 15);           // + mf*16
    int aKC  = (lane >> 4) * 16;                   // byte offset of 8-half chunk
    int g4   = lane >> 3;                          // 0..3
    int bRow = warpN * 64 + (lane & 7) + ((g4 >> 1) << 3);  // + p*16
    int bKC  = (g4 & 1) * 16;

    for (int kb = 0; kb < NKB2; kb++) {
        cp_wait<STAGES - 2>();
        __syncthreads();
        // issue next stage (overwrites stage consumed 2 iters ago; safe past barrier)
        int nk = kb + STAGES - 1;
        if (nk < NKB2) ld_stage(nk % STAGES, nk);
        cp_commit();

        uint32_t sA = smBase + (kb % STAGES) * STG_BYTES;
        uint32_t sB = sA + AS_BYTES;

        #pragma unroll
        for (int ks = 0; ks < 4; ks++) {
            uint32_t af[2][4];
            #pragma unroll
            for (int mf = 0; mf < 2; mf++) {
                uint32_t byte = (uint32_t)(aRow + mf * 16) * 128 + ks * 32 + aKC;
                ldsm4(af[mf][0], af[mf][1], af[mf][2], af[mf][3], sA + swz(byte));
            }
            uint32_t bf[8][2];
            #pragma unroll
            for (int p = 0; p < 4; p++) {
                uint32_t byte = (uint32_t)(bRow + p * 16) * 128 + ks * 32 + bKC;
                uint32_t r0, r1, r2, r3;
                ldsm4(r0, r1, r2, r3, sB + swz(byte));
                bf[2 * p][0] = r0; bf[2 * p][1] = r1;
                bf[2 * p + 1][0] = r2; bf[2 * p + 1][1] = r3;
            }
            #pragma unroll
            for (int mf = 0; mf < 2; mf++)
                #pragma unroll
                for (int nf = 0; nf < 8; nf++)
                    mma16816(acc[mf][nf], af[mf], bf[nf]);
        }
    }

    // epilogue: resid += acc
    int eRow = m0 + warpM * 32 + (lane >> 2);
    int eCol = n0 + warpN * 64 + (lane & 3) * 2;
    #pragma unroll
    for (int mf = 0; mf < 2; mf++) {
        #pragma unroll
        for (int h = 0; h < 2; h++) {          // c0c1 (row) vs c2c3 (row+8)
            int row = eRow + mf * 16 + h * 8;
            float* rp = g_resid + (size_t)row * HIDDEN + eCol;
            #pragma unroll
            for (int nf = 0; nf < 8; nf++) {
                float2 r2 = *(float2*)(rp + nf * 8);
                r2.x += acc[mf][nf][2 * h + 0];
                r2.y += acc[mf][nf][2 * h + 1];
                *(float2*)(rp + nf * 8) = r2;
            }
        }
    }
}

// ---------------- launch ------------------------------------------------------
extern "C" void kernel_launch(void* const* d_in, const int* in_sizes, int n_in,
                              void* d_out, int out_size) {
    const float* x  = (const float*)d_in[0];
    const float* g0 = (const float*)d_in[1];
    const float* g1 = (const float*)d_in[2];
    const float* g2 = (const float*)d_in[3];
    const float* g3 = (const float*)d_in[4];
    const float* W0 = (const float*)d_in[5];
    const float* W1 = (const float*)d_in[6];
    const float* W2 = (const float*)d_in[7];

    cudaFuncSetAttribute(k_gemm, cudaFuncAttributeMaxDynamicSharedMemorySize, GEMM_SMEM);

    dim3 wgrid(64, 64, 3);
    k_wprep<<<wgrid, dim3(32, 8)>>>(W0, W1, W2);
    k_prologue<<<TOKENS, 256>>>(x, g0);

    dim3 ggrid(HIDDEN / BN, TOKENS / BM);   // (16, 256)
    k_gemm<<<ggrid, 256, GEMM_SMEM>>>(0);
    k_norm<<<TOKENS, 256>>>(g1, nullptr);
    k_gemm<<<ggrid, 256, GEMM_SMEM>>>(1);
    k_norm<<<TOKENS, 256>>>(g2, nullptr);
    k_gemm<<<ggrid, 256, GEMM_SMEM>>>(2);
    k_norm<<<TOKENS, 256>>>(g3, (float*)d_out);
}